// round 15
// baseline (speedup 1.0000x reference)
#include <cuda_runtime.h>
#include <float.h>

#define BATCH 2
#define SEQ   4096
#define DIM   384
#define HEADS 6
#define HD    64
#define QK_SCALE 0.125f
#define NVP   32

__device__ float g_q[BATCH * HEADS * SEQ * HD];
__device__ float g_k[BATCH * HEADS * SEQ * HD];   // pre-rounded tf32 (RNA)
__device__ float g_v[BATCH * HEADS * SEQ * HD];   // pre-rounded tf32 (RNA)
__device__ float g_kc[BATCH * HEADS * SEQ * HD];  // compacted K
__device__ float g_vc[BATCH * HEADS * SEQ * HD];  // compacted V
__device__ float g_ao[BATCH * SEQ * DIM];         // attention out, COMPACTED rows
__device__ int   g_qidx[BATCH * SEQ];
__device__ int   g_cnt[BATCH];
__device__ float g_vsump[BATCH * HEADS * NVP * HD];
__device__ float g_od[BATCH * DIM];               // dead-row output constant

__device__ __forceinline__ unsigned tf32_of(float f) {
    unsigned u; asm("cvt.rna.tf32.f32 %0, %1;" : "=r"(u) : "f"(f)); return u;
}
__device__ __forceinline__ float tf32r(float f) { return __uint_as_float(tf32_of(f)); }
__device__ __forceinline__ void mma_tf32(float* c, const unsigned* a, const unsigned* b) {
    asm volatile("mma.sync.aligned.m16n8k8.row.col.f32.tf32.tf32.f32 "
        "{%0,%1,%2,%3}, {%4,%5,%6,%7}, {%8,%9}, {%0,%1,%2,%3};"
        : "+f"(c[0]), "+f"(c[1]), "+f"(c[2]), "+f"(c[3])
        : "r"(a[0]), "r"(a[1]), "r"(a[2]), "r"(a[3]), "r"(b[0]), "r"(b[1]));
}
#define CP16(dst, src) \
    asm volatile("cp.async.cg.shared.global [%0], [%1], 16;" :: \
        "r"((unsigned)__cvta_generic_to_shared(dst)), "l"(src))

// ---------------------------------------------------------------------------
// qkv GEMM, 2-term tf32 split (round-13 version, measured good).
// qkv -> g_q/g_k/g_v (K,V RNA-rounded).  grid (18, 64).
// ---------------------------------------------------------------------------
__global__ __launch_bounds__(256, 2) void qkv_gemm(
    const float* __restrict__ A, const float* __restrict__ w)
{
    __shared__ __align__(16) float As[2][128][20];
    __shared__ __align__(16) float Bs[2][64][20];

    const int bx = blockIdx.x, by = blockIdx.y;
    const int tid = threadIdx.x, wid = tid >> 5, l = tid & 31;
    const int lq = l >> 2, lr = l & 3;
    const int wm = (wid >> 1) * 32, wn = (wid & 1) * 32;
    const int m0 = by * 128, n0 = bx * 64;
    const int lrow = tid >> 2, lkc = (tid & 3) << 2;

    float C[2][4][4] = {};

    CP16(&As[0][lrow][lkc],      &A[(size_t)(m0 + lrow) * DIM + lkc]);
    CP16(&As[0][lrow + 64][lkc], &A[(size_t)(m0 + lrow + 64) * DIM + lkc]);
    CP16(&Bs[0][lrow][lkc],      &w[(size_t)(n0 + lrow) * DIM + lkc]);
    asm volatile("cp.async.commit_group;" ::: "memory");

    const int NITER = DIM / 16;
    for (int it = 0; it < NITER; ++it) {
        if (it + 1 < NITER) {
            int k0 = (it + 1) * 16, nb = (it + 1) & 1;
            CP16(&As[nb][lrow][lkc],      &A[(size_t)(m0 + lrow) * DIM + k0 + lkc]);
            CP16(&As[nb][lrow + 64][lkc], &A[(size_t)(m0 + lrow + 64) * DIM + k0 + lkc]);
            CP16(&Bs[nb][lrow][lkc],      &w[(size_t)(n0 + lrow) * DIM + k0 + lkc]);
            asm volatile("cp.async.commit_group;" ::: "memory");
            asm volatile("cp.async.wait_group 1;" ::: "memory");
        } else {
            asm volatile("cp.async.wait_group 0;" ::: "memory");
        }
        __syncthreads();
        const int buf = it & 1;
#pragma unroll
        for (int ks = 0; ks < 2; ++ks) {
            const int kb = ks * 8;
            unsigned ah[2][4], al[2][4], bh[4][2];
#pragma unroll
            for (int mt = 0; mt < 2; ++mt) {
                float a0 = As[buf][wm + mt * 16 + lq][kb + lr];
                float a1 = As[buf][wm + mt * 16 + lq + 8][kb + lr];
                float a2 = As[buf][wm + mt * 16 + lq][kb + lr + 4];
                float a3 = As[buf][wm + mt * 16 + lq + 8][kb + lr + 4];
                ah[mt][0] = tf32_of(a0); al[mt][0] = tf32_of(a0 - __uint_as_float(ah[mt][0]));
                ah[mt][1] = tf32_of(a1); al[mt][1] = tf32_of(a1 - __uint_as_float(ah[mt][1]));
                ah[mt][2] = tf32_of(a2); al[mt][2] = tf32_of(a2 - __uint_as_float(ah[mt][2]));
                ah[mt][3] = tf32_of(a3); al[mt][3] = tf32_of(a3 - __uint_as_float(ah[mt][3]));
            }
#pragma unroll
            for (int nt = 0; nt < 4; ++nt) {
                bh[nt][0] = tf32_of(Bs[buf][wn + nt * 8 + lq][kb + lr]);
                bh[nt][1] = tf32_of(Bs[buf][wn + nt * 8 + lq][kb + lr + 4]);
            }
#pragma unroll
            for (int mt = 0; mt < 2; ++mt)
#pragma unroll
                for (int nt = 0; nt < 4; ++nt) {
                    mma_tf32(C[mt][nt], al[mt], bh[nt]);
                    mma_tf32(C[mt][nt], ah[mt], bh[nt]);
                }
        }
        __syncthreads();
    }

    const int sel = bx / HEADS, h = bx % HEADS;
    float* dst = (sel == 0) ? g_q : (sel == 1 ? g_k : g_v);
    const bool rnd = (sel != 0);
#pragma unroll
    for (int mt = 0; mt < 2; ++mt) {
        int m = m0 + wm + mt * 16 + lq;
        float* p = dst + ((size_t)((m >> 12) * HEADS + h) * SEQ + (m & 4095)) * HD;
#pragma unroll
        for (int nt = 0; nt < 4; ++nt) {
            int n = wn + nt * 8 + lr * 2;
            float c0 = C[mt][nt][0], c1 = C[mt][nt][1];
            float c2 = C[mt][nt][2], c3 = C[mt][nt][3];
            if (rnd) { c0 = tf32r(c0); c1 = tf32r(c1); c2 = tf32r(c2); c3 = tf32r(c3); }
            *(float2*)&p[n]          = make_float2(c0, c1);
            *(float2*)&p[8 * HD + n] = make_float2(c2, c3);
        }
    }
}

// ---------------------------------------------------------------------------
// proj GEMM over LIVE rows only: A = compacted g_ao (contiguous reads),
// output scattered to orig rows. grid (6, 32, BATCH).
// ---------------------------------------------------------------------------
__global__ __launch_bounds__(256, 2) void proj_gemm(
    const float* __restrict__ w, const float* __restrict__ bias,
    float* __restrict__ out)
{
    __shared__ __align__(16) float As[2][128][20];
    __shared__ __align__(16) float Bs[2][64][20];

    const int bx = blockIdx.x, by = blockIdx.y, bz = blockIdx.z;
    const int tid = threadIdx.x, wid = tid >> 5, l = tid & 31;
    const int lq = l >> 2, lr = l & 3;
    const int wm = (wid >> 1) * 32, wn = (wid & 1) * 32;
    const int m0 = by * 128, n0 = bx * 64;
    const int lrow = tid >> 2, lkc = (tid & 3) << 2;

    const int cnt = g_cnt[bz];
    if (m0 >= cnt) return;

    // clamped contiguous A rows from compacted g_ao
    const int r0 = (m0 + lrow < cnt) ? m0 + lrow : cnt - 1;
    const int r1 = (m0 + lrow + 64 < cnt) ? m0 + lrow + 64 : cnt - 1;
    const float* A = g_ao + (size_t)bz * SEQ * DIM;

    float C[2][4][4] = {};

    CP16(&As[0][lrow][lkc],      &A[(size_t)r0 * DIM + lkc]);
    CP16(&As[0][lrow + 64][lkc], &A[(size_t)r1 * DIM + lkc]);
    CP16(&Bs[0][lrow][lkc],      &w[(size_t)(n0 + lrow) * DIM + lkc]);
    asm volatile("cp.async.commit_group;" ::: "memory");

    const int NITER = DIM / 16;
    for (int it = 0; it < NITER; ++it) {
        if (it + 1 < NITER) {
            int k0 = (it + 1) * 16, nb = (it + 1) & 1;
            CP16(&As[nb][lrow][lkc],      &A[(size_t)r0 * DIM + k0 + lkc]);
            CP16(&As[nb][lrow + 64][lkc], &A[(size_t)r1 * DIM + k0 + lkc]);
            CP16(&Bs[nb][lrow][lkc],      &w[(size_t)(n0 + lrow) * DIM + k0 + lkc]);
            asm volatile("cp.async.commit_group;" ::: "memory");
            asm volatile("cp.async.wait_group 1;" ::: "memory");
        } else {
            asm volatile("cp.async.wait_group 0;" ::: "memory");
        }
        __syncthreads();
        const int buf = it & 1;
#pragma unroll
        for (int ks = 0; ks < 2; ++ks) {
            const int kb = ks * 8;
            unsigned ah[2][4], al[2][4], bh[4][2];
#pragma unroll
            for (int mt = 0; mt < 2; ++mt) {
                float a0 = As[buf][wm + mt * 16 + lq][kb + lr];
                float a1 = As[buf][wm + mt * 16 + lq + 8][kb + lr];
                float a2 = As[buf][wm + mt * 16 + lq][kb + lr + 4];
                float a3 = As[buf][wm + mt * 16 + lq + 8][kb + lr + 4];
                ah[mt][0] = tf32_of(a0); al[mt][0] = tf32_of(a0 - __uint_as_float(ah[mt][0]));
                ah[mt][1] = tf32_of(a1); al[mt][1] = tf32_of(a1 - __uint_as_float(ah[mt][1]));
                ah[mt][2] = tf32_of(a2); al[mt][2] = tf32_of(a2 - __uint_as_float(ah[mt][2]));
                ah[mt][3] = tf32_of(a3); al[mt][3] = tf32_of(a3 - __uint_as_float(ah[mt][3]));
            }
#pragma unroll
            for (int nt = 0; nt < 4; ++nt) {
                bh[nt][0] = tf32_of(Bs[buf][wn + nt * 8 + lq][kb + lr]);
                bh[nt][1] = tf32_of(Bs[buf][wn + nt * 8 + lq][kb + lr + 4]);
            }
#pragma unroll
            for (int mt = 0; mt < 2; ++mt)
#pragma unroll
                for (int nt = 0; nt < 4; ++nt) {
                    mma_tf32(C[mt][nt], al[mt], bh[nt]);
                    mma_tf32(C[mt][nt], ah[mt], bh[nt]);
                }
        }
        __syncthreads();
    }

#pragma unroll
    for (int mt = 0; mt < 2; ++mt) {
#pragma unroll
        for (int half = 0; half < 2; ++half) {
            int m = m0 + wm + mt * 16 + lq + half * 8;
            if (m >= cnt) continue;
            int orig = g_qidx[bz * SEQ + m];
#pragma unroll
            for (int nt = 0; nt < 4; ++nt) {
                int n = n0 + wn + nt * 8 + lr * 2;
                float b0 = bias[n], b1 = bias[n + 1];
                *(float2*)&out[((size_t)bz * SEQ + orig) * DIM + n] =
                    make_float2(C[mt][nt][half * 2 + 0] + b0,
                                C[mt][nt][half * 2 + 1] + b1);
            }
        }
    }
}

// ---------------------------------------------------------------------------
__global__ __launch_bounds__(1024) void compact_kernel(const int* __restrict__ mask)
{
    __shared__ int wsum[32];
    __shared__ int base;
    const int b = blockIdx.x, t = threadIdx.x;
    const int wid = t >> 5, lane = t & 31;
    if (t == 0) base = 0;
    __syncthreads();
    for (int pass = 0; pass < SEQ / 1024; ++pass) {
        int n = pass * 1024 + t;
        int m = (mask[b * SEQ + n] != 0) ? 1 : 0;
        unsigned bal = __ballot_sync(0xffffffffu, m);
        int wpre = __popc(bal & ((1u << lane) - 1u));
        if (lane == 0) wsum[wid] = __popc(bal);
        __syncthreads();
        if (wid == 0) {
            int v = wsum[lane];
#pragma unroll
            for (int off = 1; off < 32; off <<= 1) {
                int u = __shfl_up_sync(0xffffffffu, v, off);
                if (lane >= off) v += u;
            }
            wsum[lane] = v;
        }
        __syncthreads();
        int pre = (wid > 0 ? wsum[wid - 1] : 0) + wpre;
        if (m) g_qidx[b * SEQ + base + pre] = n;
        __syncthreads();
        if (t == 0) base += wsum[31];
        __syncthreads();
    }
    if (t == 0) g_cnt[b] = base;
}

// ---------------------------------------------------------------------------
__global__ __launch_bounds__(256) void gather_kernel()
{
    const int bh = blockIdx.x, tile = blockIdx.y;
    const int b = bh / HEADS;
    const int cnt = g_cnt[b];
    const int padded = (cnt + 63) & ~63;
    if (tile * 64 >= padded) return;
    const int t = threadIdx.x;
    const int row = tile * 64 + (t >> 2);
    const int seg = (t & 3) * 16;
    const float* kb = g_k + (size_t)bh * SEQ * HD;
    const float* vb = g_v + (size_t)bh * SEQ * HD;
    float* kc = g_kc + (size_t)bh * SEQ * HD;
    float* vc = g_vc + (size_t)bh * SEQ * HD;
    float4 kv[4], vv[4];
    if (row < cnt) {
        const int src = g_qidx[b * SEQ + row];
#pragma unroll
        for (int u = 0; u < 4; ++u) {
            kv[u] = *(const float4*)&kb[(size_t)src * HD + seg + u * 4];
            vv[u] = *(const float4*)&vb[(size_t)src * HD + seg + u * 4];
        }
    } else {
#pragma unroll
        for (int u = 0; u < 4; ++u) {
            kv[u] = make_float4(0.f, 0.f, 0.f, 0.f);
            vv[u] = make_float4(0.f, 0.f, 0.f, 0.f);
        }
    }
#pragma unroll
    for (int u = 0; u < 4; ++u) {
        *(float4*)&kc[(size_t)row * HD + seg + u * 4] = kv[u];
        *(float4*)&vc[(size_t)row * HD + seg + u * 4] = vv[u];
    }
}

// vsum partials: grid (12, NVP).
__global__ __launch_bounds__(256) void vsum_kernel()
{
    __shared__ float sdata[256];
    const int bh = blockIdx.x, part = blockIdx.y;
    const int t = threadIdx.x;
    const int d = t & 63, g = t >> 6;
    const float* vb = g_v + (size_t)bh * SEQ * HD;
    float s = 0.f;
    const int r0 = part * (SEQ / NVP);
    for (int n = r0 + g; n < r0 + SEQ / NVP; n += 4) s += vb[(size_t)n * HD + d];
    sdata[t] = s;
    __syncthreads();
    if (g == 0)
        g_vsump[(bh * NVP + part) * HD + d] =
            sdata[d] + sdata[64 + d] + sdata[128 + d] + sdata[192 + d];
}

// Dead-row output constant: od[b] = (vsum/SEQ) @ w_proj^T + b_proj.
__global__ __launch_bounds__(384) void od_kernel(
    const float* __restrict__ w, const float* __restrict__ bias)
{
    __shared__ float ash[DIM];
    const int b = blockIdx.x, t = threadIdx.x;
    {
        int bh = b * HEADS + (t >> 6), d = t & 63;
        float s = 0.f;
#pragma unroll
        for (int p = 0; p < NVP; ++p) s += g_vsump[(bh * NVP + p) * HD + d];
        ash[t] = s * (1.0f / SEQ);
    }
    __syncthreads();
    float acc = bias[t];
    const float* wr = w + (size_t)t * DIM;
    for (int k = 0; k < DIM; ++k) acc += ash[k] * wr[k];
    g_od[b * DIM + t] = acc;
}

// Broadcast od to dead rows of out.
__global__ __launch_bounds__(256) void bcast_kernel(
    const int* __restrict__ mask, float* __restrict__ out)
{
    __shared__ float od[DIM];
    const int b = blockIdx.x, tile = blockIdx.y;
    const int t = threadIdx.x;
    for (int c = t; c < DIM; c += 256) od[c] = g_od[b * DIM + c];
    __syncthreads();
    for (int c = t; c < 64 * DIM; c += 256) {
        int row = tile * 64 + c / DIM;
        if (mask[b * SEQ + row] != 0) continue;
        out[((size_t)b * SEQ + row) * DIM + c % DIM] = od[c % DIM];
    }
}

// ---------------------------------------------------------------------------
// Flash attention over compacted rows/keys; writes g_ao at COMPACTED rows.
// ---------------------------------------------------------------------------
#define KS_F (64 * 68)
#define VS_F (64 * 72)
#define STG  (KS_F + VS_F)
#define ATTN_SMEM_BYTES (3 * STG * 4)

__global__ __launch_bounds__(256, 2) void attn_kernel()
{
    extern __shared__ __align__(16) float sm[];

    const int qt = blockIdx.x, bh = blockIdx.y;
    const int b = bh / HEADS, h = bh % HEADS;
    const int cnt = g_cnt[b];
    if (qt * 128 >= cnt) return;

    const int tid = threadIdx.x, w = tid >> 5, l = tid & 31;
    const int lq = l >> 2, lr = l & 3;

    const float* qbase = g_q + (size_t)bh * SEQ * HD;
    const float* kbase = g_kc + (size_t)bh * SEQ * HD;
    const float* vbase = g_vc + (size_t)bh * SEQ * HD;

    const int qrow0 = qt * 128 + w * 16 + lq;
    const int qrow1 = qrow0 + 8;
    const int ridx0 = g_qidx[b * SEQ + (qrow0 < cnt ? qrow0 : 0)];
    const int ridx1 = g_qidx[b * SEQ + (qrow1 < cnt ? qrow1 : 0)];

    const int crow = tid >> 2;
    const int cbase = (tid & 3) * 16;

    unsigned aQ[8][4];
#pragma unroll
    for (int kk = 0; kk < 8; ++kk) {
        aQ[kk][0] = tf32_of(qbase[(size_t)ridx0 * HD + kk * 8 + lr] * QK_SCALE);
        aQ[kk][1] = tf32_of(qbase[(size_t)ridx1 * HD + kk * 8 + lr] * QK_SCALE);
        aQ[kk][2] = tf32_of(qbase[(size_t)ridx0 * HD + kk * 8 + lr + 4] * QK_SCALE);
        aQ[kk][3] = tf32_of(qbase[(size_t)ridx1 * HD + kk * 8 + lr + 4] * QK_SCALE);
    }

    float O[8][4] = {};
    float m0 = -FLT_MAX, m1 = -FLT_MAX, l0 = 0.f, l1 = 0.f;

    const int NT = (cnt + 63) >> 6;

    {
        float* ks = sm; float* vs = sm + KS_F;
#pragma unroll
        for (int u = 0; u < 4; ++u) {
            int off = cbase + u * 4;
            CP16(&ks[crow * 68 + off], &kbase[(size_t)crow * HD + off]);
            CP16(&vs[crow * 72 + off], &vbase[(size_t)crow * HD + off]);
        }
        asm volatile("cp.async.commit_group;" ::: "memory");
    }

    for (int kt = 0; kt < NT; ++kt) {
        const int s = kt % 3;
        const float* ksf = sm + s * STG;
        const unsigned* ku = (const unsigned*)ksf;
        const unsigned* vu = (const unsigned*)(ksf + KS_F);

        if (kt + 1 < NT) {
            float* ks2 = sm + ((kt + 1) % 3) * STG;
            float* vs2 = ks2 + KS_F;
            const size_t nb = (size_t)(kt + 1) * 64;
#pragma unroll
            for (int u = 0; u < 4; ++u) {
                int off = cbase + u * 4;
                CP16(&ks2[crow * 68 + off], &kbase[(nb + crow) * HD + off]);
                CP16(&vs2[crow * 72 + off], &vbase[(nb + crow) * HD + off]);
            }
            asm volatile("cp.async.commit_group;" ::: "memory");
            asm volatile("cp.async.wait_group 1;" ::: "memory");
        } else {
            asm volatile("cp.async.wait_group 0;" ::: "memory");
        }
        __syncthreads();

        float sc[8][4];
#pragma unroll
        for (int nt = 0; nt < 8; ++nt) {
            sc[nt][0] = sc[nt][1] = sc[nt][2] = sc[nt][3] = 0.f;
            const unsigned* krow = ku + (nt * 8 + lq) * 68;
#pragma unroll
            for (int kk = 0; kk < 8; ++kk) {
                unsigned bk[2] = {krow[kk * 8 + lr], krow[kk * 8 + lr + 4]};
                mma_tf32(sc[nt], aQ[kk], bk);
            }
        }

        const int ktbase = kt * 64;
        float t0 = -FLT_MAX, t1 = -FLT_MAX;
#pragma unroll
        for (int nt = 0; nt < 8; ++nt) {
            int c0 = ktbase + nt * 8 + lr * 2;
            bool v0 = c0 < cnt, v1 = (c0 + 1) < cnt;
            if (!v0) { sc[nt][0] = -FLT_MAX; sc[nt][2] = -FLT_MAX; }
            if (!v1) { sc[nt][1] = -FLT_MAX; sc[nt][3] = -FLT_MAX; }
            t0 = fmaxf(t0, fmaxf(sc[nt][0], sc[nt][1]));
            t1 = fmaxf(t1, fmaxf(sc[nt][2], sc[nt][3]));
        }
        t0 = fmaxf(t0, __shfl_xor_sync(0xffffffffu, t0, 1));
        t0 = fmaxf(t0, __shfl_xor_sync(0xffffffffu, t0, 2));
        t1 = fmaxf(t1, __shfl_xor_sync(0xffffffffu, t1, 1));
        t1 = fmaxf(t1, __shfl_xor_sync(0xffffffffu, t1, 2));

        float mn0 = fmaxf(m0, t0), mn1 = fmaxf(m1, t1);
        float al0 = __expf(m0 - mn0), al1 = __expf(m1 - mn1);
        m0 = mn0; m1 = mn1;

        float ps0 = 0.f, ps1 = 0.f;
#pragma unroll
        for (int nt = 0; nt < 8; ++nt) {
            sc[nt][0] = __expf(sc[nt][0] - mn0);
            sc[nt][1] = __expf(sc[nt][1] - mn0);
            sc[nt][2] = __expf(sc[nt][2] - mn1);
            sc[nt][3] = __expf(sc[nt][3] - mn1);
            ps0 += sc[nt][0] + sc[nt][1];
            ps1 += sc[nt][2] + sc[nt][3];
        }
        ps0 += __shfl_xor_sync(0xffffffffu, ps0, 1);
        ps0 += __shfl_xor_sync(0xffffffffu, ps0, 2);
        ps1 += __shfl_xor_sync(0xffffffffu, ps1, 1);
        ps1 += __shfl_xor_sync(0xffffffffu, ps1, 2);
        l0 = l0 * al0 + ps0;
        l1 = l1 * al1 + ps1;

#pragma unroll
        for (int nt = 0; nt < 8; ++nt) {
            O[nt][0] *= al0; O[nt][1] *= al0;
            O[nt][2] *= al1; O[nt][3] *= al1;
        }

        const int srcA = (l & ~3) + (lr >> 1);
        const bool par = (lr & 1) != 0;
#pragma unroll
        for (int kk = 0; kk < 8; ++kk) {
            float x0 = __shfl_sync(0xffffffffu, sc[kk][0], srcA);
            float x1 = __shfl_sync(0xffffffffu, sc[kk][1], srcA);
            float x2 = __shfl_sync(0xffffffffu, sc[kk][2], srcA);
            float x3 = __shfl_sync(0xffffffffu, sc[kk][3], srcA);
            float y0 = __shfl_sync(0xffffffffu, sc[kk][0], srcA + 2);
            float y1 = __shfl_sync(0xffffffffu, sc[kk][1], srcA + 2);
            float y2 = __shfl_sync(0xffffffffu, sc[kk][2], srcA + 2);
            float y3 = __shfl_sync(0xffffffffu, sc[kk][3], srcA + 2);
            unsigned aP[4];
            aP[0] = tf32_of(par ? x1 : x0);
            aP[1] = tf32_of(par ? x3 : x2);
            aP[2] = tf32_of(par ? y1 : y0);
            aP[3] = tf32_of(par ? y3 : y2);
            const unsigned* vr0 = vu + (kk * 8 + lr) * 72;
            const unsigned* vr1 = vu + (kk * 8 + lr + 4) * 72;
#pragma unroll
            for (int nt = 0; nt < 8; ++nt) {
                unsigned bv[2] = {vr0[nt * 8 + lq], vr1[nt * 8 + lq]};
                mma_tf32(O[nt], aP, bv);
            }
        }
    }

    // epilogue: write COMPACTED g_ao rows (contiguous)
    const float inv0 = 1.f / l0, inv1 = 1.f / l1;
    if (qrow0 < cnt) {
        float* orow = g_ao + ((size_t)b * SEQ + qrow0) * DIM + h * HD;
#pragma unroll
        for (int nt = 0; nt < 8; ++nt) {
            int c = nt * 8 + lr * 2;
            *(float2*)&orow[c] = make_float2(O[nt][0] * inv0, O[nt][1] * inv0);
        }
    }
    if (qrow1 < cnt) {
        float* orow = g_ao + ((size_t)b * SEQ + qrow1) * DIM + h * HD;
#pragma unroll
        for (int nt = 0; nt < 8; ++nt) {
            int c = nt * 8 + lr * 2;
            *(float2*)&orow[c] = make_float2(O[nt][2] * inv1, O[nt][3] * inv1);
        }
    }
}

// ---------------------------------------------------------------------------
extern "C" void kernel_launch(void* const* d_in, const int* in_sizes, int n_in,
                              void* d_out, int out_size)
{
    const float* x      = (const float*)d_in[0];
    const int*   mask   = (const int*)d_in[1];
    const float* w_qkv  = (const float*)d_in[2];
    const float* w_proj = (const float*)d_in[3];
    const float* b_proj = (const float*)d_in[4];
    float*       out    = (float*)d_out;

    cudaFuncSetAttribute(attn_kernel,
        cudaFuncAttributeMaxDynamicSharedMemorySize, ATTN_SMEM_BYTES);

    compact_kernel<<<BATCH, 1024>>>(mask);

    qkv_gemm<<<dim3(3 * DIM / 64, (BATCH * SEQ) / 128), 256>>>(x, w_qkv);

    gather_kernel<<<dim3(BATCH * HEADS, SEQ / 64), 256>>>();
    vsum_kernel<<<dim3(BATCH * HEADS, NVP), 256>>>();

    attn_kernel<<<dim3(SEQ / 128, BATCH * HEADS), 256, ATTN_SMEM_BYTES>>>();

    od_kernel<<<BATCH, 384>>>(w_proj, b_proj);
    bcast_kernel<<<dim3(BATCH, SEQ / 64), 256>>>(mask, out);

    proj_gemm<<<dim3(DIM / 64, SEQ / 128, BATCH), 256>>>(w_proj, b_proj, out);
}

// round 16
// speedup vs baseline: 1.1906x; 1.1906x over previous
#include <cuda_runtime.h>
#include <float.h>

#define BATCH 2
#define SEQ   4096
#define DIM   384
#define HEADS 6
#define HD    64
#define QK_SCALE 0.125f
#define NVP   32

__device__ float g_q [BATCH * HEADS * SEQ * HD];  // full Q (raw fp32)
__device__ float g_v [BATCH * HEADS * SEQ * HD];  // full V (tf32 RNA, for vsum)
__device__ float g_kc[BATCH * HEADS * SEQ * HD];  // compacted K (tf32 RNA)
__device__ float g_vc[BATCH * HEADS * SEQ * HD];  // compacted V (tf32 RNA)
__device__ float g_ao[BATCH * SEQ * DIM];
__device__ int   g_qidx[BATCH * SEQ];             // compacted -> orig
__device__ int   g_pos [BATCH * SEQ];             // orig -> compacted (-1 dead)
__device__ int   g_cnt[BATCH];
__device__ float g_vsump[BATCH * HEADS * NVP * HD];

__device__ __forceinline__ unsigned tf32_of(float f) {
    unsigned u; asm("cvt.rna.tf32.f32 %0, %1;" : "=r"(u) : "f"(f)); return u;
}
__device__ __forceinline__ float tf32r(float f) { return __uint_as_float(tf32_of(f)); }
__device__ __forceinline__ void mma_tf32(float* c, const unsigned* a, const unsigned* b) {
    asm volatile("mma.sync.aligned.m16n8k8.row.col.f32.tf32.tf32.f32 "
        "{%0,%1,%2,%3}, {%4,%5,%6,%7}, {%8,%9}, {%0,%1,%2,%3};"
        : "+f"(c[0]), "+f"(c[1]), "+f"(c[2]), "+f"(c[3])
        : "r"(a[0]), "r"(a[1]), "r"(a[2]), "r"(a[3]), "r"(b[0]), "r"(b[1]));
}
#define CP16(dst, src) \
    asm volatile("cp.async.cg.shared.global [%0], [%1], 16;" :: \
        "r"((unsigned)__cvta_generic_to_shared(dst)), "l"(src))

// ---------------------------------------------------------------------------
// qkv GEMM, 2-term tf32 split (round-13 mainloop). Epilogue fuses compaction:
// Q -> g_q full; K -> g_kc[pos] (RNA); V -> g_v full + g_vc[pos] (RNA).
// grid (18, 64).
// ---------------------------------------------------------------------------
__global__ __launch_bounds__(256, 2) void qkv_gemm(
    const float* __restrict__ A, const float* __restrict__ w)
{
    __shared__ __align__(16) float As[2][128][20];
    __shared__ __align__(16) float Bs[2][64][20];

    const int bx = blockIdx.x, by = blockIdx.y;
    const int tid = threadIdx.x, wid = tid >> 5, l = tid & 31;
    const int lq = l >> 2, lr = l & 3;
    const int wm = (wid >> 1) * 32, wn = (wid & 1) * 32;
    const int m0 = by * 128, n0 = bx * 64;
    const int lrow = tid >> 2, lkc = (tid & 3) << 2;

    float C[2][4][4] = {};

    CP16(&As[0][lrow][lkc],      &A[(size_t)(m0 + lrow) * DIM + lkc]);
    CP16(&As[0][lrow + 64][lkc], &A[(size_t)(m0 + lrow + 64) * DIM + lkc]);
    CP16(&Bs[0][lrow][lkc],      &w[(size_t)(n0 + lrow) * DIM + lkc]);
    asm volatile("cp.async.commit_group;" ::: "memory");

    const int NITER = DIM / 16;
    for (int it = 0; it < NITER; ++it) {
        if (it + 1 < NITER) {
            int k0 = (it + 1) * 16, nb = (it + 1) & 1;
            CP16(&As[nb][lrow][lkc],      &A[(size_t)(m0 + lrow) * DIM + k0 + lkc]);
            CP16(&As[nb][lrow + 64][lkc], &A[(size_t)(m0 + lrow + 64) * DIM + k0 + lkc]);
            CP16(&Bs[nb][lrow][lkc],      &w[(size_t)(n0 + lrow) * DIM + k0 + lkc]);
            asm volatile("cp.async.commit_group;" ::: "memory");
            asm volatile("cp.async.wait_group 1;" ::: "memory");
        } else {
            asm volatile("cp.async.wait_group 0;" ::: "memory");
        }
        __syncthreads();
        const int buf = it & 1;
#pragma unroll
        for (int ks = 0; ks < 2; ++ks) {
            const int kb = ks * 8;
            unsigned ah[2][4], al[2][4], bh[4][2];
#pragma unroll
            for (int mt = 0; mt < 2; ++mt) {
                float a0 = As[buf][wm + mt * 16 + lq][kb + lr];
                float a1 = As[buf][wm + mt * 16 + lq + 8][kb + lr];
                float a2 = As[buf][wm + mt * 16 + lq][kb + lr + 4];
                float a3 = As[buf][wm + mt * 16 + lq + 8][kb + lr + 4];
                ah[mt][0] = tf32_of(a0); al[mt][0] = tf32_of(a0 - __uint_as_float(ah[mt][0]));
                ah[mt][1] = tf32_of(a1); al[mt][1] = tf32_of(a1 - __uint_as_float(ah[mt][1]));
                ah[mt][2] = tf32_of(a2); al[mt][2] = tf32_of(a2 - __uint_as_float(ah[mt][2]));
                ah[mt][3] = tf32_of(a3); al[mt][3] = tf32_of(a3 - __uint_as_float(ah[mt][3]));
            }
#pragma unroll
            for (int nt = 0; nt < 4; ++nt) {
                bh[nt][0] = tf32_of(Bs[buf][wn + nt * 8 + lq][kb + lr]);
                bh[nt][1] = tf32_of(Bs[buf][wn + nt * 8 + lq][kb + lr + 4]);
            }
#pragma unroll
            for (int mt = 0; mt < 2; ++mt)
#pragma unroll
                for (int nt = 0; nt < 4; ++nt) {
                    mma_tf32(C[mt][nt], al[mt], bh[nt]);
                    mma_tf32(C[mt][nt], ah[mt], bh[nt]);
                }
        }
        __syncthreads();
    }

    const int sel = bx / HEADS, h = bx % HEADS;
    if (sel == 0) {
        // Q: full layout, raw fp32 (identical to round 13)
#pragma unroll
        for (int mt = 0; mt < 2; ++mt) {
            int m = m0 + wm + mt * 16 + lq;
            float* p = g_q + ((size_t)((m >> 12) * HEADS + h) * SEQ + (m & 4095)) * HD;
#pragma unroll
            for (int nt = 0; nt < 4; ++nt) {
                int n = wn + nt * 8 + lr * 2;
                *(float2*)&p[n]          = make_float2(C[mt][nt][0], C[mt][nt][1]);
                *(float2*)&p[8 * HD + n] = make_float2(C[mt][nt][2], C[mt][nt][3]);
            }
        }
    } else {
        // K/V: RNA-round; K -> g_kc[pos]; V -> g_v full + g_vc[pos]
#pragma unroll
        for (int mt = 0; mt < 2; ++mt) {
#pragma unroll
            for (int half = 0; half < 2; ++half) {
                int m = m0 + wm + mt * 16 + lq + half * 8;
                int b = m >> 12, nn = m & 4095;
                int pos = g_pos[b * SEQ + nn];
                size_t bhs = (size_t)(b * HEADS + h) * SEQ;
#pragma unroll
                for (int nt = 0; nt < 4; ++nt) {
                    int n = wn + nt * 8 + lr * 2;
                    float c0 = tf32r(C[mt][nt][half * 2 + 0]);
                    float c1 = tf32r(C[mt][nt][half * 2 + 1]);
                    if (sel == 1) {
                        if (pos >= 0)
                            *(float2*)&g_kc[(bhs + pos) * HD + n] = make_float2(c0, c1);
                    } else {
                        *(float2*)&g_v[(bhs + nn) * HD + n] = make_float2(c0, c1);
                        if (pos >= 0)
                            *(float2*)&g_vc[(bhs + pos) * HD + n] = make_float2(c0, c1);
                    }
                }
            }
        }
    }
}

// ---------------------------------------------------------------------------
// Compaction: ballot/popc warp scan; also writes orig->compacted map g_pos.
// ---------------------------------------------------------------------------
__global__ __launch_bounds__(1024) void compact_kernel(const int* __restrict__ mask)
{
    __shared__ int wsum[32];
    __shared__ int base;
    const int b = blockIdx.x, t = threadIdx.x;
    const int wid = t >> 5, lane = t & 31;
    if (t == 0) base = 0;
    __syncthreads();
    for (int pass = 0; pass < SEQ / 1024; ++pass) {
        int n = pass * 1024 + t;
        int m = (mask[b * SEQ + n] != 0) ? 1 : 0;
        unsigned bal = __ballot_sync(0xffffffffu, m);
        int wpre = __popc(bal & ((1u << lane) - 1u));
        if (lane == 0) wsum[wid] = __popc(bal);
        __syncthreads();
        if (wid == 0) {
            int v = wsum[lane];
#pragma unroll
            for (int off = 1; off < 32; off <<= 1) {
                int u = __shfl_up_sync(0xffffffffu, v, off);
                if (lane >= off) v += u;
            }
            wsum[lane] = v;
        }
        __syncthreads();
        int pre = (wid > 0 ? wsum[wid - 1] : 0) + wpre;
        int dest = base + pre;
        g_pos[b * SEQ + n] = m ? dest : -1;
        if (m) g_qidx[b * SEQ + dest] = n;
        __syncthreads();
        if (t == 0) base += wsum[31];
        __syncthreads();
    }
    if (t == 0) g_cnt[b] = base;
}

// Zero padding rows [cnt, padded) of g_kc and g_vc per (b,h).
__global__ __launch_bounds__(256) void pad_kernel()
{
    const int bh = blockIdx.x, b = bh / HEADS;
    const int cnt = g_cnt[b];
    const int padded = (cnt + 63) & ~63;
    float* kc = g_kc + (size_t)bh * SEQ * HD;
    float* vc = g_vc + (size_t)bh * SEQ * HD;
    const int nfl = (padded - cnt) * HD;
    for (int i = threadIdx.x; i < nfl; i += 256) {
        kc[(size_t)cnt * HD + i] = 0.f;
        vc[(size_t)cnt * HD + i] = 0.f;
    }
}

// vsum partials: grid (12, NVP).
__global__ __launch_bounds__(256) void vsum_kernel()
{
    __shared__ float sdata[256];
    const int bh = blockIdx.x, part = blockIdx.y;
    const int t = threadIdx.x;
    const int d = t & 63, g = t >> 6;
    const float* vb = g_v + (size_t)bh * SEQ * HD;
    float s = 0.f;
    const int r0 = part * (SEQ / NVP);
    for (int n = r0 + g; n < r0 + SEQ / NVP; n += 4) s += vb[(size_t)n * HD + d];
    sdata[t] = s;
    __syncthreads();
    if (g == 0)
        g_vsump[(bh * NVP + part) * HD + d] =
            sdata[d] + sdata[64 + d] + sdata[128 + d] + sdata[192 + d];
}

// Dead rows -> g_ao = vsum / SEQ.
__global__ __launch_bounds__(256) void fill_dead_kernel(const int* __restrict__ mask)
{
    __shared__ float vsh[DIM];
    const int b = blockIdx.x, tile = blockIdx.y;
    const int t = threadIdx.x;
    const float inv = 1.0f / SEQ;
    for (int c = t; c < DIM; c += 256) {
        int bh = b * HEADS + (c >> 6), d = c & 63;
        float s = 0.f;
#pragma unroll
        for (int p = 0; p < NVP; ++p) s += g_vsump[(bh * NVP + p) * HD + d];
        vsh[c] = s * inv;
    }
    __syncthreads();
    for (int c = t; c < 64 * DIM; c += 256) {
        int row = tile * 64 + c / DIM;
        int col = c % DIM;
        if (mask[b * SEQ + row] != 0) continue;
        g_ao[((size_t)b * SEQ + row) * DIM + col] = vsh[col];
    }
}

// ---------------------------------------------------------------------------
// proj GEMM over all rows (round-13 version, dense, g_ao full layout).
// ---------------------------------------------------------------------------
__global__ __launch_bounds__(256, 2) void proj_gemm(
    const float* __restrict__ w, const float* __restrict__ bias,
    float* __restrict__ out)
{
    __shared__ __align__(16) float As[2][128][20];
    __shared__ __align__(16) float Bs[2][64][20];

    const int bx = blockIdx.x, by = blockIdx.y;
    const int tid = threadIdx.x, wid = tid >> 5, l = tid & 31;
    const int lq = l >> 2, lr = l & 3;
    const int wm = (wid >> 1) * 32, wn = (wid & 1) * 32;
    const int m0 = by * 128, n0 = bx * 64;
    const int lrow = tid >> 2, lkc = (tid & 3) << 2;

    float C[2][4][4] = {};

    CP16(&As[0][lrow][lkc],      &g_ao[(size_t)(m0 + lrow) * DIM + lkc]);
    CP16(&As[0][lrow + 64][lkc], &g_ao[(size_t)(m0 + lrow + 64) * DIM + lkc]);
    CP16(&Bs[0][lrow][lkc],      &w[(size_t)(n0 + lrow) * DIM + lkc]);
    asm volatile("cp.async.commit_group;" ::: "memory");

    const int NITER = DIM / 16;
    for (int it = 0; it < NITER; ++it) {
        if (it + 1 < NITER) {
            int k0 = (it + 1) * 16, nb = (it + 1) & 1;
            CP16(&As[nb][lrow][lkc],      &g_ao[(size_t)(m0 + lrow) * DIM + k0 + lkc]);
            CP16(&As[nb][lrow + 64][lkc], &g_ao[(size_t)(m0 + lrow + 64) * DIM + k0 + lkc]);
            CP16(&Bs[nb][lrow][lkc],      &w[(size_t)(n0 + lrow) * DIM + k0 + lkc]);
            asm volatile("cp.async.commit_group;" ::: "memory");
            asm volatile("cp.async.wait_group 1;" ::: "memory");
        } else {
            asm volatile("cp.async.wait_group 0;" ::: "memory");
        }
        __syncthreads();
        const int buf = it & 1;
#pragma unroll
        for (int ks = 0; ks < 2; ++ks) {
            const int kb = ks * 8;
            unsigned ah[2][4], al[2][4], bh[4][2];
#pragma unroll
            for (int mt = 0; mt < 2; ++mt) {
                float a0 = As[buf][wm + mt * 16 + lq][kb + lr];
                float a1 = As[buf][wm + mt * 16 + lq + 8][kb + lr];
                float a2 = As[buf][wm + mt * 16 + lq][kb + lr + 4];
                float a3 = As[buf][wm + mt * 16 + lq + 8][kb + lr + 4];
                ah[mt][0] = tf32_of(a0); al[mt][0] = tf32_of(a0 - __uint_as_float(ah[mt][0]));
                ah[mt][1] = tf32_of(a1); al[mt][1] = tf32_of(a1 - __uint_as_float(ah[mt][1]));
                ah[mt][2] = tf32_of(a2); al[mt][2] = tf32_of(a2 - __uint_as_float(ah[mt][2]));
                ah[mt][3] = tf32_of(a3); al[mt][3] = tf32_of(a3 - __uint_as_float(ah[mt][3]));
            }
#pragma unroll
            for (int nt = 0; nt < 4; ++nt) {
                bh[nt][0] = tf32_of(Bs[buf][wn + nt * 8 + lq][kb + lr]);
                bh[nt][1] = tf32_of(Bs[buf][wn + nt * 8 + lq][kb + lr + 4]);
            }
#pragma unroll
            for (int mt = 0; mt < 2; ++mt)
#pragma unroll
                for (int nt = 0; nt < 4; ++nt) {
                    mma_tf32(C[mt][nt], al[mt], bh[nt]);
                    mma_tf32(C[mt][nt], ah[mt], bh[nt]);
                }
        }
        __syncthreads();
    }

#pragma unroll
    for (int mt = 0; mt < 2; ++mt) {
        int m = m0 + wm + mt * 16 + lq;
#pragma unroll
        for (int nt = 0; nt < 4; ++nt) {
            int n = n0 + wn + nt * 8 + lr * 2;
            float b0 = bias[n], b1 = bias[n + 1];
            *(float2*)&out[(size_t)m * DIM + n] =
                make_float2(C[mt][nt][0] + b0, C[mt][nt][1] + b1);
            *(float2*)&out[(size_t)(m + 8) * DIM + n] =
                make_float2(C[mt][nt][2] + b0, C[mt][nt][3] + b1);
        }
    }
}

// ---------------------------------------------------------------------------
// Flash attention over compacted rows/keys (round-13 version).
// ---------------------------------------------------------------------------
#define KS_F (64 * 68)
#define VS_F (64 * 72)
#define STG  (KS_F + VS_F)
#define ATTN_SMEM_BYTES (3 * STG * 4)

__global__ __launch_bounds__(256, 2) void attn_kernel()
{
    extern __shared__ __align__(16) float sm[];

    const int qt = blockIdx.x, bh = blockIdx.y;
    const int b = bh / HEADS, h = bh % HEADS;
    const int cnt = g_cnt[b];
    if (qt * 128 >= cnt) return;

    const int tid = threadIdx.x, w = tid >> 5, l = tid & 31;
    const int lq = l >> 2, lr = l & 3;

    const float* qbase = g_q + (size_t)bh * SEQ * HD;
    const float* kbase = g_kc + (size_t)bh * SEQ * HD;
    const float* vbase = g_vc + (size_t)bh * SEQ * HD;

    const int qrow0 = qt * 128 + w * 16 + lq;
    const int qrow1 = qrow0 + 8;
    const int ridx0 = g_qidx[b * SEQ + (qrow0 < cnt ? qrow0 : 0)];
    const int ridx1 = g_qidx[b * SEQ + (qrow1 < cnt ? qrow1 : 0)];

    const int crow = tid >> 2;
    const int cbase = (tid & 3) * 16;

    unsigned aQ[8][4];
#pragma unroll
    for (int kk = 0; kk < 8; ++kk) {
        aQ[kk][0] = tf32_of(qbase[(size_t)ridx0 * HD + kk * 8 + lr] * QK_SCALE);
        aQ[kk][1] = tf32_of(qbase[(size_t)ridx1 * HD + kk * 8 + lr] * QK_SCALE);
        aQ[kk][2] = tf32_of(qbase[(size_t)ridx0 * HD + kk * 8 + lr + 4] * QK_SCALE);
        aQ[kk][3] = tf32_of(qbase[(size_t)ridx1 * HD + kk * 8 + lr + 4] * QK_SCALE);
    }

    float O[8][4] = {};
    float m0 = -FLT_MAX, m1 = -FLT_MAX, l0 = 0.f, l1 = 0.f;

    const int NT = (cnt + 63) >> 6;

    {
        float* ks = sm; float* vs = sm + KS_F;
#pragma unroll
        for (int u = 0; u < 4; ++u) {
            int off = cbase + u * 4;
            CP16(&ks[crow * 68 + off], &kbase[(size_t)crow * HD + off]);
            CP16(&vs[crow * 72 + off], &vbase[(size_t)crow * HD + off]);
        }
        asm volatile("cp.async.commit_group;" ::: "memory");
    }

    for (int kt = 0; kt < NT; ++kt) {
        const int s = kt % 3;
        const float* ksf = sm + s * STG;
        const unsigned* ku = (const unsigned*)ksf;
        const unsigned* vu = (const unsigned*)(ksf + KS_F);

        if (kt + 1 < NT) {
            float* ks2 = sm + ((kt + 1) % 3) * STG;
            float* vs2 = ks2 + KS_F;
            const size_t nb = (size_t)(kt + 1) * 64;
#pragma unroll
            for (int u = 0; u < 4; ++u) {
                int off = cbase + u * 4;
                CP16(&ks2[crow * 68 + off], &kbase[(nb + crow) * HD + off]);
                CP16(&vs2[crow * 72 + off], &vbase[(nb + crow) * HD + off]);
            }
            asm volatile("cp.async.commit_group;" ::: "memory");
            asm volatile("cp.async.wait_group 1;" ::: "memory");
        } else {
            asm volatile("cp.async.wait_group 0;" ::: "memory");
        }
        __syncthreads();

        float sc[8][4];
#pragma unroll
        for (int nt = 0; nt < 8; ++nt) {
            sc[nt][0] = sc[nt][1] = sc[nt][2] = sc[nt][3] = 0.f;
            const unsigned* krow = ku + (nt * 8 + lq) * 68;
#pragma unroll
            for (int kk = 0; kk < 8; ++kk) {
                unsigned bk[2] = {krow[kk * 8 + lr], krow[kk * 8 + lr + 4]};
                mma_tf32(sc[nt], aQ[kk], bk);
            }
        }

        const int ktbase = kt * 64;
        float t0 = -FLT_MAX, t1 = -FLT_MAX;
#pragma unroll
        for (int nt = 0; nt < 8; ++nt) {
            int c0 = ktbase + nt * 8 + lr * 2;
            bool v0 = c0 < cnt, v1 = (c0 + 1) < cnt;
            if (!v0) { sc[nt][0] = -FLT_MAX; sc[nt][2] = -FLT_MAX; }
            if (!v1) { sc[nt][1] = -FLT_MAX; sc[nt][3] = -FLT_MAX; }
            t0 = fmaxf(t0, fmaxf(sc[nt][0], sc[nt][1]));
            t1 = fmaxf(t1, fmaxf(sc[nt][2], sc[nt][3]));
        }
        t0 = fmaxf(t0, __shfl_xor_sync(0xffffffffu, t0, 1));
        t0 = fmaxf(t0, __shfl_xor_sync(0xffffffffu, t0, 2));
        t1 = fmaxf(t1, __shfl_xor_sync(0xffffffffu, t1, 1));
        t1 = fmaxf(t1, __shfl_xor_sync(0xffffffffu, t1, 2));

        float mn0 = fmaxf(m0, t0), mn1 = fmaxf(m1, t1);
        float al0 = __expf(m0 - mn0), al1 = __expf(m1 - mn1);
        m0 = mn0; m1 = mn1;

        float ps0 = 0.f, ps1 = 0.f;
#pragma unroll
        for (int nt = 0; nt < 8; ++nt) {
            sc[nt][0] = __expf(sc[nt][0] - mn0);
            sc[nt][1] = __expf(sc[nt][1] - mn0);
            sc[nt][2] = __expf(sc[nt][2] - mn1);
            sc[nt][3] = __expf(sc[nt][3] - mn1);
            ps0 += sc[nt][0] + sc[nt][1];
            ps1 += sc[nt][2] + sc[nt][3];
        }
        ps0 += __shfl_xor_sync(0xffffffffu, ps0, 1);
        ps0 += __shfl_xor_sync(0xffffffffu, ps0, 2);
        ps1 += __shfl_xor_sync(0xffffffffu, ps1, 1);
        ps1 += __shfl_xor_sync(0xffffffffu, ps1, 2);
        l0 = l0 * al0 + ps0;
        l1 = l1 * al1 + ps1;

#pragma unroll
        for (int nt = 0; nt < 8; ++nt) {
            O[nt][0] *= al0; O[nt][1] *= al0;
            O[nt][2] *= al1; O[nt][3] *= al1;
        }

        const int srcA = (l & ~3) + (lr >> 1);
        const bool par = (lr & 1) != 0;
#pragma unroll
        for (int kk = 0; kk < 8; ++kk) {
            float x0 = __shfl_sync(0xffffffffu, sc[kk][0], srcA);
            float x1 = __shfl_sync(0xffffffffu, sc[kk][1], srcA);
            float x2 = __shfl_sync(0xffffffffu, sc[kk][2], srcA);
            float x3 = __shfl_sync(0xffffffffu, sc[kk][3], srcA);
            float y0 = __shfl_sync(0xffffffffu, sc[kk][0], srcA + 2);
            float y1 = __shfl_sync(0xffffffffu, sc[kk][1], srcA + 2);
            float y2 = __shfl_sync(0xffffffffu, sc[kk][2], srcA + 2);
            float y3 = __shfl_sync(0xffffffffu, sc[kk][3], srcA + 2);
            unsigned aP[4];
            aP[0] = tf32_of(par ? x1 : x0);
            aP[1] = tf32_of(par ? x3 : x2);
            aP[2] = tf32_of(par ? y1 : y0);
            aP[3] = tf32_of(par ? y3 : y2);
            const unsigned* vr0 = vu + (kk * 8 + lr) * 72;
            const unsigned* vr1 = vu + (kk * 8 + lr + 4) * 72;
#pragma unroll
            for (int nt = 0; nt < 8; ++nt) {
                unsigned bv[2] = {vr0[nt * 8 + lq], vr1[nt * 8 + lq]};
                mma_tf32(O[nt], aP, bv);
            }
        }
    }

    const float inv0 = 1.f / l0, inv1 = 1.f / l1;
    if (qrow0 < cnt) {
        float* orow = g_ao + ((size_t)b * SEQ + ridx0) * DIM + h * HD;
#pragma unroll
        for (int nt = 0; nt < 8; ++nt) {
            int c = nt * 8 + lr * 2;
            *(float2*)&orow[c] = make_float2(O[nt][0] * inv0, O[nt][1] * inv0);
        }
    }
    if (qrow1 < cnt) {
        float* orow = g_ao + ((size_t)b * SEQ + ridx1) * DIM + h * HD;
#pragma unroll
        for (int nt = 0; nt < 8; ++nt) {
            int c = nt * 8 + lr * 2;
            *(float2*)&orow[c] = make_float2(O[nt][2] * inv1, O[nt][3] * inv1);
        }
    }
}

// ---------------------------------------------------------------------------
extern "C" void kernel_launch(void* const* d_in, const int* in_sizes, int n_in,
                              void* d_out, int out_size)
{
    const float* x      = (const float*)d_in[0];
    const int*   mask   = (const int*)d_in[1];
    const float* w_qkv  = (const float*)d_in[2];
    const float* w_proj = (const float*)d_in[3];
    const float* b_proj = (const float*)d_in[4];
    float*       out    = (float*)d_out;

    cudaFuncSetAttribute(attn_kernel,
        cudaFuncAttributeMaxDynamicSharedMemorySize, ATTN_SMEM_BYTES);

    compact_kernel<<<BATCH, 1024>>>(mask);

    qkv_gemm<<<dim3(3 * DIM / 64, (BATCH * SEQ) / 128), 256>>>(x, w_qkv);

    pad_kernel<<<BATCH * HEADS, 256>>>();
    vsum_kernel<<<dim3(BATCH * HEADS, NVP), 256>>>();

    attn_kernel<<<dim3(SEQ / 128, BATCH * HEADS), 256, ATTN_SMEM_BYTES>>>();

    fill_dead_kernel<<<dim3(BATCH, SEQ / 64), 256>>>(mask);

    proj_gemm<<<dim3(DIM / 64, (BATCH * SEQ) / 128), 256>>>(w_proj, b_proj, out);
}